// round 2
// baseline (speedup 1.0000x reference)
#include <cuda_runtime.h>

// Problem constants
#define N_B   4
#define L_SEQ 1024
#define DM    1024
#define NH    16
#define DH    64
#define MROWS (N_B * L_SEQ)   // 4096
#define MAXSEQ 2048

// Scratch (device globals; no allocation allowed)
__device__ float g_Q[N_B * NH * L_SEQ * DH];   // [n][h][l][d]
__device__ float g_K[N_B * NH * L_SEQ * DH];
__device__ float g_V[N_B * NH * L_SEQ * DH];
__device__ float g_O[N_B * L_SEQ * DM];        // [n][l][h*64+d]

// ---------------------------------------------------------------------------
// GEMM: C[M=4096, N=1024] = A[4096,1024] @ W[1024,1024] + bias
// MODE 0: scatter into head-split layout g_X[((n*16+h)*1024+l)*64+d]
// MODE 1: plain row-major output
// 128x128 block tile, BK=16, 256 threads, 8x8 microtile per thread.
// ---------------------------------------------------------------------------
#define BM 128
#define BN 128
#define BK 16

template <int MODE>
__global__ void __launch_bounds__(256) gemm_bias_kernel(
    const float* __restrict__ A, const float* __restrict__ W,
    const float* __restrict__ bias, float* __restrict__ C)
{
    __shared__ float As[BK][BM + 4];   // As[k][m] (transposed store)
    __shared__ float Bs[BK][BN];       // Bs[k][n]

    const int tid  = threadIdx.x;
    const int tx   = tid & 15;
    const int ty   = tid >> 4;
    const int row0 = blockIdx.y * BM;
    const int col0 = blockIdx.x * BN;

    float acc[8][8];
#pragma unroll
    for (int i = 0; i < 8; i++)
#pragma unroll
        for (int j = 0; j < 8; j++) acc[i][j] = 0.f;

    for (int k0 = 0; k0 < DM; k0 += BK) {
        // Load A tile (128 rows x 16 k), transpose into As[k][m]
#pragma unroll
        for (int i = 0; i < 2; i++) {
            int f  = tid + i * 256;          // 0..511
            int m  = f >> 2;                 // 0..127
            int kq = (f & 3) << 2;           // 0,4,8,12
            float4 v = *reinterpret_cast<const float4*>(
                &A[(size_t)(row0 + m) * DM + k0 + kq]);
            As[kq + 0][m] = v.x;
            As[kq + 1][m] = v.y;
            As[kq + 2][m] = v.z;
            As[kq + 3][m] = v.w;
        }
        // Load B tile (16 k x 128 cols)
#pragma unroll
        for (int i = 0; i < 2; i++) {
            int f  = tid + i * 256;          // 0..511
            int kk = f >> 5;                 // 0..15
            int c4 = (f & 31) << 2;          // 0..124
            *reinterpret_cast<float4*>(&Bs[kk][c4]) =
                *reinterpret_cast<const float4*>(
                    &W[(size_t)(k0 + kk) * DM + col0 + c4]);
        }
        __syncthreads();

#pragma unroll
        for (int kk = 0; kk < BK; kk++) {
            float4 a0 = *reinterpret_cast<const float4*>(&As[kk][ty * 8]);
            float4 a1 = *reinterpret_cast<const float4*>(&As[kk][ty * 8 + 4]);
            float4 b0 = *reinterpret_cast<const float4*>(&Bs[kk][tx * 8]);
            float4 b1 = *reinterpret_cast<const float4*>(&Bs[kk][tx * 8 + 4]);
            float av[8] = {a0.x, a0.y, a0.z, a0.w, a1.x, a1.y, a1.z, a1.w};
            float bv[8] = {b0.x, b0.y, b0.z, b0.w, b1.x, b1.y, b1.z, b1.w};
#pragma unroll
            for (int i = 0; i < 8; i++)
#pragma unroll
                for (int j = 0; j < 8; j++) acc[i][j] += av[i] * bv[j];
        }
        __syncthreads();
    }

    // Epilogue: bias + store
#pragma unroll
    for (int i = 0; i < 8; i++) {
        int r = row0 + ty * 8 + i;
#pragma unroll
        for (int j = 0; j < 8; j += 4) {
            int c = col0 + tx * 8 + j;
            float4 v;
            v.x = acc[i][j + 0] + bias[c + 0];
            v.y = acc[i][j + 1] + bias[c + 1];
            v.z = acc[i][j + 2] + bias[c + 2];
            v.w = acc[i][j + 3] + bias[c + 3];
            if (MODE == 0) {
                int n = r >> 10, l = r & 1023;
                int h = c >> 6, d = c & 63;
                size_t idx = ((size_t)((n * NH + h) * L_SEQ + l) << 6) + d;
                *reinterpret_cast<float4*>(&C[idx]) = v;
            } else {
                *reinterpret_cast<float4*>(&C[(size_t)r * DM + c]) = v;
            }
        }
    }
}

// ---------------------------------------------------------------------------
// Flash attention with relative-position bias.
// One block per (n,h, 64-row query tile). 256 threads.
// bias[qi][kj] = q[qi] . pos_emb[2047 - qi + kj]   (causal region only)
// Per key-tile: load K^T, E^T; compute QE[64][128]; S=QK^T + diag-shifted QE;
// online softmax; P@V.
// ---------------------------------------------------------------------------
#define SMEM_FLOATS (2 * 64 * 68 + 2 * 64 * 132)   // 25600 floats = 100 KB
#define SMEM_BYTES  (SMEM_FLOATS * 4)

__global__ void __launch_bounds__(256) attn_kernel(const float* __restrict__ pos_emb)
{
    extern __shared__ float sm[];
    float* Qt = sm;                          // [64][68]  Qt[d][a]
    float* KV = sm + 64 * 68;                // [64][68]  Kt[d][b]  -> later Vs[b][c]
    float* EP = sm + 2 * 64 * 68;            // [64][132] Et[d][c]  -> later Ps[a][b] stride 68
    float* QE = sm + 2 * 64 * 68 + 64 * 132; // [64][132] QEs[a][c]

    const int tid = threadIdx.x;
    const int tx  = tid & 15;
    const int ty  = tid >> 4;
    const int qt  = 15 - blockIdx.x;   // heavy tiles first
    const int nh  = blockIdx.y;        // n*16 + h
    const int qt0 = qt * 64;
    const size_t headbase = (size_t)nh * L_SEQ * DH;

    // Load Q tile transposed: Qt[d][a]
    {
        const float* src = g_Q + headbase + (size_t)qt0 * DH;
#pragma unroll
        for (int i = 0; i < 4; i++) {
            int f  = tid + i * 256;
            int a  = f >> 4;
            int dq = (f & 15) << 2;
            float4 v = *reinterpret_cast<const float4*>(&src[a * DH + dq]);
            Qt[(dq + 0) * 68 + a] = v.x;
            Qt[(dq + 1) * 68 + a] = v.y;
            Qt[(dq + 2) * 68 + a] = v.z;
            Qt[(dq + 3) * 68 + a] = v.w;
        }
    }

    float m_run[4], l_run[4], o[4][4];
#pragma unroll
    for (int i = 0; i < 4; i++) {
        m_run[i] = -1e30f;
        l_run[i] = 0.f;
#pragma unroll
        for (int j = 0; j < 4; j++) o[i][j] = 0.f;
    }
    __syncthreads();

    for (int kt = 0; kt <= qt; kt++) {
        const int kt0 = kt * 64;
        const int r0  = 1984 - qt0 + kt0;   // >= 1024 always

        // ---- phase A: load K^T and E^T ----
        {
            const float* src = g_K + headbase + (size_t)kt0 * DH;
#pragma unroll
            for (int i = 0; i < 4; i++) {
                int f  = tid + i * 256;
                int b  = f >> 4;
                int dq = (f & 15) << 2;
                float4 v = *reinterpret_cast<const float4*>(&src[b * DH + dq]);
                KV[(dq + 0) * 68 + b] = v.x;
                KV[(dq + 1) * 68 + b] = v.y;
                KV[(dq + 2) * 68 + b] = v.z;
                KV[(dq + 3) * 68 + b] = v.w;
            }
#pragma unroll
            for (int i = 0; i < 8; i++) {
                int f  = tid + i * 256;      // 0..2047
                int c  = f >> 4;             // 0..127
                int dq = (f & 15) << 2;
                int r  = r0 + c;
                float4 v = make_float4(0.f, 0.f, 0.f, 0.f);
                if (r < MAXSEQ)
                    v = *reinterpret_cast<const float4*>(&pos_emb[(size_t)r * DH + dq]);
                EP[(dq + 0) * 132 + c] = v.x;
                EP[(dq + 1) * 132 + c] = v.y;
                EP[(dq + 2) * 132 + c] = v.z;
                EP[(dq + 3) * 132 + c] = v.w;
            }
        }
        __syncthreads();

        // ---- phase B: QE[64][128] = Q @ E^T  (4x8 microtile) ----
        {
            const int a0 = ty * 4;
            const int c0 = tx * 8;
            float qe[4][8];
#pragma unroll
            for (int i = 0; i < 4; i++)
#pragma unroll
                for (int j = 0; j < 8; j++) qe[i][j] = 0.f;
#pragma unroll 8
            for (int d = 0; d < 64; d++) {
                float4 qa = *reinterpret_cast<const float4*>(&Qt[d * 68 + a0]);
                float4 e0 = *reinterpret_cast<const float4*>(&EP[d * 132 + c0]);
                float4 e1 = *reinterpret_cast<const float4*>(&EP[d * 132 + c0 + 4]);
                float av[4] = {qa.x, qa.y, qa.z, qa.w};
                float ev[8] = {e0.x, e0.y, e0.z, e0.w, e1.x, e1.y, e1.z, e1.w};
#pragma unroll
                for (int i = 0; i < 4; i++)
#pragma unroll
                    for (int j = 0; j < 8; j++) qe[i][j] += av[i] * ev[j];
            }
#pragma unroll
            for (int i = 0; i < 4; i++) {
                *reinterpret_cast<float4*>(&QE[(a0 + i) * 132 + c0]) =
                    make_float4(qe[i][0], qe[i][1], qe[i][2], qe[i][3]);
                *reinterpret_cast<float4*>(&QE[(a0 + i) * 132 + c0 + 4]) =
                    make_float4(qe[i][4], qe[i][5], qe[i][6], qe[i][7]);
            }
        }
        __syncthreads();

        // ---- phase C: S = QK^T, add bias, mask, online softmax, write P ----
        {
            const int a0 = ty * 4;
            const int b0 = tx * 4;
            float s[4][4];
#pragma unroll
            for (int i = 0; i < 4; i++)
#pragma unroll
                for (int j = 0; j < 4; j++) s[i][j] = 0.f;
#pragma unroll 8
            for (int d = 0; d < 64; d++) {
                float4 qa = *reinterpret_cast<const float4*>(&Qt[d * 68 + a0]);
                float4 kb = *reinterpret_cast<const float4*>(&KV[d * 68 + b0]);
                float av[4] = {qa.x, qa.y, qa.z, qa.w};
                float bv[4] = {kb.x, kb.y, kb.z, kb.w};
#pragma unroll
                for (int i = 0; i < 4; i++)
#pragma unroll
                    for (int j = 0; j < 4; j++) s[i][j] += av[i] * bv[j];
            }
#pragma unroll
            for (int ai = 0; ai < 4; ai++) {
                int a = a0 + ai;
#pragma unroll
                for (int bi = 0; bi < 4; bi++) {
                    int b = b0 + bi;
                    float logit = (s[ai][bi] + QE[a * 132 + 63 - a + b]) * 0.125f;
                    bool valid  = (kt0 + b) <= (qt0 + a);
                    s[ai][bi]   = valid ? logit : -1e30f;
                }
            }
            // online softmax (row reduce over the 16 tx lanes of a half-warp)
#pragma unroll
            for (int ai = 0; ai < 4; ai++) {
                float tm = fmaxf(fmaxf(s[ai][0], s[ai][1]), fmaxf(s[ai][2], s[ai][3]));
#pragma unroll
                for (int off = 1; off < 16; off <<= 1)
                    tm = fmaxf(tm, __shfl_xor_sync(0xffffffffu, tm, off));
                float mn    = fmaxf(m_run[ai], tm);
                float alpha = __expf(m_run[ai] - mn);
                float rs    = 0.f;
#pragma unroll
                for (int bi = 0; bi < 4; bi++) {
                    float p = __expf(s[ai][bi] - mn);
                    s[ai][bi] = p;
                    rs += p;
                }
#pragma unroll
                for (int off = 1; off < 16; off <<= 1)
                    rs += __shfl_xor_sync(0xffffffffu, rs, off);
                l_run[ai] = l_run[ai] * alpha + rs;
                m_run[ai] = mn;
#pragma unroll
                for (int ci = 0; ci < 4; ci++) o[ai][ci] *= alpha;
            }
            // write P into EP (stride 68); Et reads all completed at phase-B barrier
#pragma unroll
            for (int ai = 0; ai < 4; ai++)
#pragma unroll
                for (int bi = 0; bi < 4; bi++)
                    EP[(a0 + ai) * 68 + b0 + bi] = s[ai][bi];
        }
        __syncthreads();

        // ---- phase D: load V over K ----
        {
            const float* src = g_V + headbase + (size_t)kt0 * DH;
#pragma unroll
            for (int i = 0; i < 4; i++) {
                int f  = tid + i * 256;
                int b  = f >> 4;
                int cq = (f & 15) << 2;
                *reinterpret_cast<float4*>(&KV[b * 68 + cq]) =
                    *reinterpret_cast<const float4*>(&src[b * DH + cq]);
            }
        }
        __syncthreads();

        // ---- phase E: O += P @ V ----
        {
            const int a0 = ty * 4;
            const int c0 = tx * 4;
#pragma unroll 16
            for (int b = 0; b < 64; b++) {
                float4 vv = *reinterpret_cast<const float4*>(&KV[b * 68 + c0]);
                float p0 = EP[(a0 + 0) * 68 + b];
                float p1 = EP[(a0 + 1) * 68 + b];
                float p2 = EP[(a0 + 2) * 68 + b];
                float p3 = EP[(a0 + 3) * 68 + b];
                o[0][0] += p0 * vv.x; o[0][1] += p0 * vv.y; o[0][2] += p0 * vv.z; o[0][3] += p0 * vv.w;
                o[1][0] += p1 * vv.x; o[1][1] += p1 * vv.y; o[1][2] += p1 * vv.z; o[1][3] += p1 * vv.w;
                o[2][0] += p2 * vv.x; o[2][1] += p2 * vv.y; o[2][2] += p2 * vv.z; o[2][3] += p2 * vv.w;
                o[3][0] += p3 * vv.x; o[3][1] += p3 * vv.y; o[3][2] += p3 * vv.z; o[3][3] += p3 * vv.w;
            }
        }
        __syncthreads();   // protects KV/EP reuse next iteration
    }

    // Epilogue: normalize and write to g_O [n][l][h*64 + c]
    const int n = nh >> 4;
    const int h = nh & 15;
#pragma unroll
    for (int ai = 0; ai < 4; ai++) {
        int row = qt0 + ty * 4 + ai;
        float inv = 1.f / l_run[ai];
        float4 v = make_float4(o[ai][0] * inv, o[ai][1] * inv,
                               o[ai][2] * inv, o[ai][3] * inv);
        *reinterpret_cast<float4*>(
            &g_O[(size_t)(n * L_SEQ + row) * DM + h * DH + tx * 4]) = v;
    }
}

// ---------------------------------------------------------------------------
extern "C" void kernel_launch(void* const* d_in, const int* in_sizes, int n_in,
                              void* d_out, int out_size)
{
    const float* q_in    = (const float*)d_in[0];
    const float* k_in    = (const float*)d_in[1];
    const float* v_in    = (const float*)d_in[2];
    // d_in[3] = mask (strict causal triu; implemented analytically)
    const float* Wq      = (const float*)d_in[4];
    const float* bq      = (const float*)d_in[5];
    const float* Wk      = (const float*)d_in[6];
    const float* bk      = (const float*)d_in[7];
    const float* Wv      = (const float*)d_in[8];
    const float* bv      = (const float*)d_in[9];
    const float* Wo      = (const float*)d_in[10];
    const float* bo      = (const float*)d_in[11];
    const float* pos_emb = (const float*)d_in[12];

    float *pQ, *pK, *pV, *pO;
    cudaGetSymbolAddress((void**)&pQ, g_Q);
    cudaGetSymbolAddress((void**)&pK, g_K);
    cudaGetSymbolAddress((void**)&pV, g_V);
    cudaGetSymbolAddress((void**)&pO, g_O);

    cudaFuncSetAttribute(attn_kernel,
                         cudaFuncAttributeMaxDynamicSharedMemorySize, SMEM_BYTES);

    dim3 ggrid(DM / BN, MROWS / BM);   // (8, 32)
    gemm_bias_kernel<0><<<ggrid, 256>>>(q_in, Wq, bq, pQ);
    gemm_bias_kernel<0><<<ggrid, 256>>>(k_in, Wk, bk, pK);
    gemm_bias_kernel<0><<<ggrid, 256>>>(v_in, Wv, bv, pV);

    attn_kernel<<<dim3(16, N_B * NH), 256, SMEM_BYTES>>>(pos_emb);

    gemm_bias_kernel<1><<<ggrid, 256>>>(pO, Wo, bo, (float*)d_out);
}

// round 7
// speedup vs baseline: 2.2798x; 2.2798x over previous
#include <cuda_runtime.h>
#include <cuda_bf16.h>

// Problem constants
#define N_B   4
#define L_SEQ 1024
#define DM    1024
#define NH    16
#define DH    64
#define MROWS (N_B * L_SEQ)   // 4096
#define MAXSEQ 2048
#define HSZ   (N_B * NH * L_SEQ * DH)   // 4M

// ---------------------------------------------------------------------------
// Global scratch (split bf16 hi/lo pairs) — arena-reused, ~72 MB total
// ---------------------------------------------------------------------------
__device__ __nv_bfloat16 g_ah[MROWS * DM], g_al[MROWS * DM];  // input split / attn out
__device__ __nv_bfloat16 g_wh[DM * DM],    g_wl[DM * DM];     // current weight split
__device__ __nv_bfloat16 g_qh[HSZ], g_ql[HSZ];                // head-split Q
__device__ __nv_bfloat16 g_kh[HSZ], g_kl[HSZ];
__device__ __nv_bfloat16 g_vh[HSZ], g_vl[HSZ];
__device__ __nv_bfloat16 g_eh[MAXSEQ * DH], g_el[MAXSEQ * DH];// pos_emb

// ---------------------------------------------------------------------------
// helpers
// ---------------------------------------------------------------------------
__device__ __forceinline__ void bsplit(float x, __nv_bfloat16& h, __nv_bfloat16& l) {
    h = __float2bfloat16(x);
    l = __float2bfloat16(x - __bfloat162float(h));
}

// D(16x8,f32) += A(16x16,bf16,row) * B(16x8,bf16,col)
__device__ __forceinline__ void mma16(float* c, const unsigned* a, const unsigned* b) {
    asm volatile(
        "mma.sync.aligned.m16n8k16.row.col.f32.bf16.bf16.f32 "
        "{%0,%1,%2,%3}, {%4,%5,%6,%7}, {%8,%9}, {%0,%1,%2,%3};"
        : "+f"(c[0]), "+f"(c[1]), "+f"(c[2]), "+f"(c[3])
        : "r"(a[0]), "r"(a[1]), "r"(a[2]), "r"(a[3]), "r"(b[0]), "r"(b[1]));
}

__device__ __forceinline__ void cp16(void* dst, const void* src) {
    unsigned d = (unsigned)__cvta_generic_to_shared(dst);
    asm volatile("cp.async.cg.shared.global [%0], [%1], 16;" :: "r"(d), "l"(src));
}

// A fragment from row-major [m][k] tile; SW = stride in 32-bit words.
template <int SW>
__device__ __forceinline__ void ldA(const __nv_bfloat16* T, int r, int kw, int col, unsigned* a) {
    const unsigned* w = reinterpret_cast<const unsigned*>(T) + r * SW + kw + col;
    a[0] = w[0]; a[1] = w[8 * SW]; a[2] = w[4]; a[3] = w[8 * SW + 4];
}
// B fragment from row-major [n][k] tile (k contiguous); SW = word stride.
template <int SW>
__device__ __forceinline__ void ldB(const __nv_bfloat16* T, int n, int kw, int col, unsigned* b) {
    const unsigned* w = reinterpret_cast<const unsigned*>(T) + n * SW + kw + col;
    b[0] = w[0]; b[1] = w[4];
}
// B fragment from row-major [k][n] tile (transposed read); SH = stride in halves.
template <int SH>
__device__ __forceinline__ void ldBt(const __nv_bfloat16* T, int k, int n, unsigned* b) {
    const unsigned short* p = reinterpret_cast<const unsigned short*>(T) + k * SH + n;
    b[0] = (unsigned)p[0]      | ((unsigned)p[SH]     << 16);
    b[1] = (unsigned)p[8 * SH] | ((unsigned)p[9 * SH] << 16);
}

// ---------------------------------------------------------------------------
// Elementwise fp32 -> (bf16 hi, bf16 lo) split
// ---------------------------------------------------------------------------
__global__ void __launch_bounds__(256) split_kernel(
    const float* __restrict__ in, __nv_bfloat16* __restrict__ h,
    __nv_bfloat16* __restrict__ l, int n)
{
    int i = (blockIdx.x * 256 + threadIdx.x) * 4;
    if (i >= n) return;
    float4 v = *reinterpret_cast<const float4*>(in + i);
    __nv_bfloat16 h0, h1, h2, h3, l0, l1, l2, l3;
    bsplit(v.x, h0, l0); bsplit(v.y, h1, l1);
    bsplit(v.z, h2, l2); bsplit(v.w, h3, l3);
    *reinterpret_cast<__nv_bfloat162*>(h + i)     = __nv_bfloat162(h0, h1);
    *reinterpret_cast<__nv_bfloat162*>(h + i + 2) = __nv_bfloat162(h2, h3);
    *reinterpret_cast<__nv_bfloat162*>(l + i)     = __nv_bfloat162(l0, l1);
    *reinterpret_cast<__nv_bfloat162*>(l + i + 2) = __nv_bfloat162(l2, l3);
}

// ---------------------------------------------------------------------------
// Split-bf16 GEMM: C[4096,1024] = (Ah+Al) @ (Wh+Wl) + bias
// MODE 0: split outputs into head-split bf16 hi/lo arrays.
// MODE 1: fp32 row-major output.
// 128x128 block, BK=32, 256 threads, 8 warps (2x4, 64x32 warp tiles),
// cp.async double buffering.
// ---------------------------------------------------------------------------
#define GBK  32
#define GAS  40     // A tile stride (bf16)
#define GBS  136    // B tile stride (bf16)
#define GA_SZ (128 * GAS)   // 5120 bf16 per component
#define GB_SZ (GBK * GBS)   // 4352 bf16 per component
#define GBUF  (2 * GA_SZ + 2 * GB_SZ)
#define GSMEM_BYTES (2 * GBUF * 2)   // 75776

template <int MODE>
__global__ void __launch_bounds__(256) gemm_split(
    const __nv_bfloat16* __restrict__ Agh, const __nv_bfloat16* __restrict__ Agl,
    const __nv_bfloat16* __restrict__ Wgh, const __nv_bfloat16* __restrict__ Wgl,
    const float* __restrict__ bias, float* __restrict__ C32,
    __nv_bfloat16* __restrict__ Cbh, __nv_bfloat16* __restrict__ Cbl)
{
    extern __shared__ __nv_bfloat16 gsm[];

    const int tid  = threadIdx.x;
    const int lane = tid & 31, wid = tid >> 5;
    const int row  = lane >> 2, col = lane & 3;
    const int wm   = (wid & 1) << 6;
    const int wn   = (wid >> 1) << 5;
    const int row0 = blockIdx.y << 7;
    const int col0 = blockIdx.x << 7;

    float acc[4][4][4];
#pragma unroll
    for (int i = 0; i < 4; i++)
#pragma unroll
        for (int j = 0; j < 4; j++)
#pragma unroll
            for (int k = 0; k < 4; k++) acc[i][j][k] = 0.f;

    auto fill = [&](int buf, int k0) {
        __nv_bfloat16* Ah = gsm + buf * GBUF;
        __nv_bfloat16* Al = Ah + GA_SZ;
        __nv_bfloat16* Bh = Al + GA_SZ;
        __nv_bfloat16* Bl = Bh + GB_SZ;
#pragma unroll
        for (int i = 0; i < 2; i++) {
            int f = tid + i * 256;          // 0..511
            int m = f >> 2, ch = f & 3;
            cp16(Ah + m * GAS + ch * 8, Agh + (size_t)(row0 + m) * DM + k0 + ch * 8);
            cp16(Al + m * GAS + ch * 8, Agl + (size_t)(row0 + m) * DM + k0 + ch * 8);
        }
#pragma unroll
        for (int i = 0; i < 2; i++) {
            int f = tid + i * 256;          // 0..511
            int kk = f >> 4, ch = f & 15;
            cp16(Bh + kk * GBS + ch * 8, Wgh + (size_t)(k0 + kk) * DM + col0 + ch * 8);
            cp16(Bl + kk * GBS + ch * 8, Wgl + (size_t)(k0 + kk) * DM + col0 + ch * 8);
        }
        asm volatile("cp.async.commit_group;");
    };

    fill(0, 0);

    for (int t = 0; t < DM / GBK; t++) {
        const int buf = t & 1;
        if (t + 1 < DM / GBK) {
            fill(buf ^ 1, (t + 1) * GBK);
            asm volatile("cp.async.wait_group 1;");
        } else {
            asm volatile("cp.async.wait_group 0;");
        }
        __syncthreads();

        const __nv_bfloat16* Ah = gsm + buf * GBUF;
        const __nv_bfloat16* Al = Ah + GA_SZ;
        const __nv_bfloat16* Bh = Al + GA_SZ;
        const __nv_bfloat16* Bl = Bh + GB_SZ;

#pragma unroll
        for (int ks = 0; ks < GBK / 16; ks++) {
            unsigned ah[4][4], al[4][4], bh[4][2], bl[4][2];
#pragma unroll
            for (int i = 0; i < 4; i++) {
                ldA<GAS / 2>(Ah, wm + i * 16 + row, ks * 8, col, ah[i]);
                ldA<GAS / 2>(Al, wm + i * 16 + row, ks * 8, col, al[i]);
            }
            const int kb = ks * 16 + col * 2;
#pragma unroll
            for (int j = 0; j < 4; j++) {
                ldBt<GBS>(Bh, kb, wn + j * 8 + row, bh[j]);
                ldBt<GBS>(Bl, kb, wn + j * 8 + row, bl[j]);
            }
#pragma unroll
            for (int i = 0; i < 4; i++)
#pragma unroll
                for (int j = 0; j < 4; j++) {
                    mma16(acc[i][j], ah[i], bh[j]);
                    mma16(acc[i][j], ah[i], bl[j]);
                    mma16(acc[i][j], al[i], bh[j]);
                }
        }
        __syncthreads();
    }

    // Epilogue
#pragma unroll
    for (int i = 0; i < 4; i++) {
#pragma unroll
        for (int j = 0; j < 4; j++) {
            int r = row0 + wm + i * 16 + row;
            int c = col0 + wn + j * 8 + 2 * col;
            float bx = bias[c], by = bias[c + 1];
            float v00 = acc[i][j][0] + bx, v01 = acc[i][j][1] + by;
            float v10 = acc[i][j][2] + bx, v11 = acc[i][j][3] + by;
            if (MODE == 0) {
                int n = r >> 10, h = c >> 6, d = c & 63;
                int l0 = r & 1023, l1 = (r + 8) & 1023;
                size_t i0 = ((size_t)((n * NH + h) * L_SEQ + l0) << 6) + d;
                size_t i1 = ((size_t)((n * NH + h) * L_SEQ + l1) << 6) + d;
                __nv_bfloat16 h0, h1, lo0, lo1;
                bsplit(v00, h0, lo0); bsplit(v01, h1, lo1);
                *reinterpret_cast<__nv_bfloat162*>(Cbh + i0) = __nv_bfloat162(h0, h1);
                *reinterpret_cast<__nv_bfloat162*>(Cbl + i0) = __nv_bfloat162(lo0, lo1);
                bsplit(v10, h0, lo0); bsplit(v11, h1, lo1);
                *reinterpret_cast<__nv_bfloat162*>(Cbh + i1) = __nv_bfloat162(h0, h1);
                *reinterpret_cast<__nv_bfloat162*>(Cbl + i1) = __nv_bfloat162(lo0, lo1);
            } else {
                *reinterpret_cast<float2*>(&C32[(size_t)r * DM + c]) = make_float2(v00, v01);
                *reinterpret_cast<float2*>(&C32[(size_t)(r + 8) * DM + c]) = make_float2(v10, v11);
            }
        }
    }
}

// ---------------------------------------------------------------------------
// Split-bf16 flash attention with relative-position bias.
// Block = (n,h, 64-row q-tile), 256 threads (8 warps).
// ---------------------------------------------------------------------------
#define AST 72              // bf16 stride for Q/K/V/E/P tiles
#define ASW (AST / 2)       // 36 words
#define STE 132             // fp32 stride for QE
#define TQ  (64 * AST)      // 4608 bf16 per component
#define TE  (128 * AST)     // 9216 bf16 per component
// bytes: (4*TQ + 2*TE)*2 + (64*STE + 384)*4 = 73728 + 35328 = 109056
#define ASM_BYTES 109056

__global__ void __launch_bounds__(256) attn_split()
{
    extern __shared__ __nv_bfloat16 asm_[];
    __nv_bfloat16* Qh  = asm_;             // [64][72]
    __nv_bfloat16* Ql  = Qh + TQ;
    __nv_bfloat16* KVh = Ql + TQ;          // [64][72]  K[b][d] -> V[b][c]
    __nv_bfloat16* KVl = KVh + TQ;
    __nv_bfloat16* Eh  = KVl + TQ;         // [128][72] E[c][d]; rows 0..63 reused for P[a][b]
    __nv_bfloat16* El  = Eh + TE;
    float* QEs   = reinterpret_cast<float*>(El + TE);  // [64][132]
    float* pmax  = QEs + 64 * STE;         // [2][64]
    float* psum  = pmax + 128;             // [2][64]
    float* m_run = psum + 128;             // [64]
    float* l_run = m_run + 64;             // [64]

    const int tid  = threadIdx.x;
    const int lane = tid & 31, wid = tid >> 5;
    const int row  = lane >> 2, col = lane & 3;

    const int qt  = 15 - blockIdx.x;   // heavy tiles first
    const int nh  = blockIdx.y;
    const int qt0 = qt * 64;
    const size_t headbase = (size_t)nh * L_SEQ * DH;

    const int wmB = (wid & 1) * 32;
    const int wnB = (wid >> 1) * 32;
    const int wmC = (wid & 3) * 16;
    const int wnC4 = wid >> 2;
    const int wnC = wnC4 * 32;
    const int r1 = wmC + row, r2 = r1 + 8;

    if (tid < 64) { m_run[tid] = -1e30f; l_run[tid] = 0.f; }

    // Q tile (cp.async)
    {
        const size_t base = headbase + (size_t)qt0 * DH;
#pragma unroll
        for (int i = 0; i < 2; i++) {
            int f = tid + i * 256;      // 0..511
            int a = f >> 3, ch = f & 7;
            cp16(Qh + a * AST + ch * 8, g_qh + base + a * DH + ch * 8);
            cp16(Ql + a * AST + ch * 8, g_ql + base + a * DH + ch * 8);
        }
        asm volatile("cp.async.commit_group;");
    }

    float o[4][4];
#pragma unroll
    for (int j = 0; j < 4; j++)
#pragma unroll
        for (int k = 0; k < 4; k++) o[j][k] = 0.f;

    for (int kt = 0; kt <= qt; kt++) {
        const int kt0 = kt * 64;
        const int r0  = 1984 - qt0 + kt0;
        const int dqk = qt0 - kt0;

        // ---- phase A: cp.async K and E (E rows clamped; clamped rows only
        //      feed causally-masked bias columns) ----
        {
            const size_t base = headbase + (size_t)kt0 * DH;
#pragma unroll
            for (int i = 0; i < 2; i++) {
                int f = tid + i * 256;
                int b = f >> 3, ch = f & 7;
                cp16(KVh + b * AST + ch * 8, g_kh + base + b * DH + ch * 8);
                cp16(KVl + b * AST + ch * 8, g_kl + base + b * DH + ch * 8);
            }
#pragma unroll
            for (int i = 0; i < 4; i++) {
                int f = tid + i * 256;      // 0..1023
                int c = f >> 3, ch = f & 7;
                int r = r0 + c;
                r = (r < MAXSEQ) ? r : (MAXSEQ - 1);
                cp16(Eh + c * AST + ch * 8, g_eh + (size_t)r * DH + ch * 8);
                cp16(El + c * AST + ch * 8, g_el + (size_t)r * DH + ch * 8);
            }
            asm volatile("cp.async.commit_group;");
            asm volatile("cp.async.wait_group 0;");
        }
        __syncthreads();

        // ---- phase B: QE = Q @ E^T ----
        {
            float qe[2][4][4];
#pragma unroll
            for (int i = 0; i < 2; i++)
#pragma unroll
                for (int j = 0; j < 4; j++)
#pragma unroll
                    for (int k = 0; k < 4; k++) qe[i][j][k] = 0.f;
#pragma unroll
            for (int ks = 0; ks < 4; ks++) {
                unsigned ah[2][4], al[2][4], bh[4][2], bl[4][2];
#pragma unroll
                for (int i = 0; i < 2; i++) {
                    ldA<ASW>(Qh, wmB + i * 16 + row, ks * 8, col, ah[i]);
                    ldA<ASW>(Ql, wmB + i * 16 + row, ks * 8, col, al[i]);
                }
#pragma unroll
                for (int j = 0; j < 4; j++) {
                    ldB<ASW>(Eh, wnB + j * 8 + row, ks * 8, col, bh[j]);
                    ldB<ASW>(El, wnB + j * 8 + row, ks * 8, col, bl[j]);
                }
#pragma unroll
                for (int i = 0; i < 2; i++)
#pragma unroll
                    for (int j = 0; j < 4; j++) {
                        mma16(qe[i][j], ah[i], bh[j]);
                        mma16(qe[i][j], ah[i], bl[j]);
                        mma16(qe[i][j], al[i], bh[j]);
                    }
            }
#pragma unroll
            for (int i = 0; i < 2; i++) {
                int aa = wmB + i * 16 + row;
#pragma unroll
                for (int j = 0; j < 4; j++) {
                    int cc = wnB + j * 8 + 2 * col;
                    *reinterpret_cast<float2*>(&QEs[aa * STE + cc]) =
                        make_float2(qe[i][j][0], qe[i][j][1]);
                    *reinterpret_cast<float2*>(&QEs[(aa + 8) * STE + cc]) =
                        make_float2(qe[i][j][2], qe[i][j][3]);
                }
            }
        }
        __syncthreads();

        // ---- phase C: S = Q @ K^T, bias, mask, online softmax ----
        float s[4][4];
#pragma unroll
        for (int j = 0; j < 4; j++)
#pragma unroll
            for (int k = 0; k < 4; k++) s[j][k] = 0.f;
#pragma unroll
        for (int ks = 0; ks < 4; ks++) {
            unsigned ah[4], al[4], bh[4][2], bl[4][2];
            ldA<ASW>(Qh, wmC + row, ks * 8, col, ah);
            ldA<ASW>(Ql, wmC + row, ks * 8, col, al);
#pragma unroll
            for (int j = 0; j < 4; j++) {
                ldB<ASW>(KVh, wnC + j * 8 + row, ks * 8, col, bh[j]);
                ldB<ASW>(KVl, wnC + j * 8 + row, ks * 8, col, bl[j]);
            }
#pragma unroll
            for (int j = 0; j < 4; j++) {
                mma16(s[j], ah, bh[j]);
                mma16(s[j], ah, bl[j]);
                mma16(s[j], al, bh[j]);
            }
        }
        {
            const int limit1 = dqk + r1, limit2 = dqk + r2;
            float mx1 = -1e30f, mx2 = -1e30f;
#pragma unroll
            for (int j = 0; j < 4; j++) {
                int bb = wnC + j * 8 + 2 * col;
                float qe10 = QEs[r1 * STE + 63 - r1 + bb];
                float qe11 = QEs[r1 * STE + 63 - r1 + bb + 1];
                float qe20 = QEs[r2 * STE + 63 - r2 + bb];
                float qe21 = QEs[r2 * STE + 63 - r2 + bb + 1];
                s[j][0] = (bb     <= limit1) ? (s[j][0] + qe10) * 0.125f : -1e30f;
                s[j][1] = (bb + 1 <= limit1) ? (s[j][1] + qe11) * 0.125f : -1e30f;
                s[j][2] = (bb     <= limit2) ? (s[j][2] + qe20) * 0.125f : -1e30f;
                s[j][3] = (bb + 1 <= limit2) ? (s[j][3] + qe21) * 0.125f : -1e30f;
                mx1 = fmaxf(mx1, fmaxf(s[j][0], s[j][1]));
                mx2 = fmaxf(mx2, fmaxf(s[j][2], s[j][3]));
            }
            mx1 = fmaxf(mx1, __shfl_xor_sync(0xffffffffu, mx1, 1));
            mx1 = fmaxf(mx1, __shfl_xor_sync(0xffffffffu, mx1, 2));
            mx2 = fmaxf(mx2, __shfl_xor_sync(0xffffffffu, mx2, 1));
            mx2 = fmaxf(mx2, __shfl_xor_sync(0xffffffffu, mx2, 2));
            if (col == 0) {
                pmax[wnC4 * 64 + r1] = mx1;
                pmax[wnC4 * 64 + r2] = mx2;
            }
            __syncthreads();

            float newm1 = fmaxf(m_run[r1], fmaxf(pmax[r1], pmax[64 + r1]));
            float newm2 = fmaxf(m_run[r2], fmaxf(pmax[r2], pmax[64 + r2]));
            float alpha1 = __expf(m_run[r1] - newm1);
            float alpha2 = __expf(m_run[r2] - newm2);
            float sum1 = 0.f, sum2 = 0.f;
#pragma unroll
            for (int j = 0; j < 4; j++) {
                int bb = wnC + j * 8 + 2 * col;
                float p0 = __expf(s[j][0] - newm1);
                float p1 = __expf(s[j][1] - newm1);
                float p2 = __expf(s[j][2] - newm2);
                float p3 = __expf(s[j][3] - newm2);
                sum1 += p0 + p1; sum2 += p2 + p3;
                __nv_bfloat16 h0, h1, l0, l1;
                bsplit(p0, h0, l0); bsplit(p1, h1, l1);
                *reinterpret_cast<__nv_bfloat162*>(&Eh[r1 * AST + bb]) = __nv_bfloat162(h0, h1);
                *reinterpret_cast<__nv_bfloat162*>(&El[r1 * AST + bb]) = __nv_bfloat162(l0, l1);
                bsplit(p2, h0, l0); bsplit(p3, h1, l1);
                *reinterpret_cast<__nv_bfloat162*>(&Eh[r2 * AST + bb]) = __nv_bfloat162(h0, h1);
                *reinterpret_cast<__nv_bfloat162*>(&El[r2 * AST + bb]) = __nv_bfloat162(l0, l1);
            }
            sum1 += __shfl_xor_sync(0xffffffffu, sum1, 1);
            sum1 += __shfl_xor_sync(0xffffffffu, sum1, 2);
            sum2 += __shfl_xor_sync(0xffffffffu, sum2, 1);
            sum2 += __shfl_xor_sync(0xffffffffu, sum2, 2);
            if (col == 0) {
                psum[wnC4 * 64 + r1] = sum1;
                psum[wnC4 * 64 + r2] = sum2;
            }
#pragma unroll
            for (int j = 0; j < 4; j++) {
                o[j][0] *= alpha1; o[j][1] *= alpha1;
                o[j][2] *= alpha2; o[j][3] *= alpha2;
            }
            __syncthreads();   // psum/P ready; all K-frag reads done

            if (wnC4 == 0 && col == 0) {
                l_run[r1] = l_run[r1] * alpha1 + psum[r1] + psum[64 + r1];
                l_run[r2] = l_run[r2] * alpha2 + psum[r2] + psum[64 + r2];
                m_run[r1] = newm1;
                m_run[r2] = newm2;
            }
        }

        // ---- phase D: cp.async V over K (row-major [b][c], no transpose) ----
        {
            const size_t base = headbase + (size_t)kt0 * DH;
#pragma unroll
            for (int i = 0; i < 2; i++) {
                int f = tid + i * 256;
                int b = f >> 3, ch = f & 7;
                cp16(KVh + b * AST + ch * 8, g_vh + base + b * DH + ch * 8);
                cp16(KVl + b * AST + ch * 8, g_vl + base + b * DH + ch * 8);
            }
            asm volatile("cp.async.commit_group;");
            asm volatile("cp.async.wait_group 0;");
        }
        __syncthreads();

        // ---- phase E: O += P @ V  (B-frag = V^T via u16 composition) ----
#pragma unroll
        for (int ks = 0; ks < 4; ks++) {
            unsigned ah[4], al[4], bh[4][2], bl[4][2];
            ldA<ASW>(Eh, wmC + row, ks * 8, col, ah);   // P hi
            ldA<ASW>(El, wmC + row, ks * 8, col, al);   // P lo
            const int kb = ks * 16 + col * 2;
#pragma unroll
            for (int j = 0; j < 4; j++) {
                ldBt<AST>(KVh, kb, wnC + j * 8 + row, bh[j]);
                ldBt<AST>(KVl, kb, wnC + j * 8 + row, bl[j]);
            }
#pragma unroll
            for (int j = 0; j < 4; j++) {
                mma16(o[j], ah, bh[j]);
                mma16(o[j], ah, bl[j]);
                mma16(o[j], al, bh[j]);
            }
        }
        __syncthreads();   // tile buffers free for next iteration
    }

    // Epilogue: normalize, split, write g_ah/g_al [n][l][h*64+c]
    {
        const int n = nh >> 4, h = nh & 15;
        float inv1 = 1.f / l_run[r1];
        float inv2 = 1.f / l_run[r2];
#pragma unroll
        for (int j = 0; j < 4; j++) {
            int cc = wnC + j * 8 + 2 * col;
            size_t a1 = (size_t)(n * L_SEQ + qt0 + r1) * DM + h * DH + cc;
            size_t a2 = (size_t)(n * L_SEQ + qt0 + r2) * DM + h * DH + cc;
            __nv_bfloat16 h0, h1, l0, l1;
            bsplit(o[j][0] * inv1, h0, l0); bsplit(o[j][1] * inv1, h1, l1);
            *reinterpret_cast<__nv_bfloat162*>(g_ah + a1) = __nv_bfloat162(h0, h1);
            *reinterpret_cast<__nv_bfloat162*>(g_al + a1) = __nv_bfloat162(l0, l1);
            bsplit(o[j][2] * inv2, h0, l0); bsplit(o[j][3] * inv2, h1, l1);
            *reinterpret_cast<__nv_bfloat162*>(g_ah + a2) = __nv_bfloat162(h0, h1);
            *reinterpret_cast<__nv_bfloat162*>(g_al + a2) = __nv_bfloat162(l0, l1);
        }
    }
}

// ---------------------------------------------------------------------------
extern "C" void kernel_launch(void* const* d_in, const int* in_sizes, int n_in,
                              void* d_out, int out_size)
{
    const float* q_in    = (const float*)d_in[0];
    const float* k_in    = (const float*)d_in[1];
    const float* v_in    = (const float*)d_in[2];
    // d_in[3] = mask (strict causal; analytic)
    const float* Wq      = (const float*)d_in[4];
    const float* bq      = (const float*)d_in[5];
    const float* Wk      = (const float*)d_in[6];
    const float* bk      = (const float*)d_in[7];
    const float* Wv      = (const float*)d_in[8];
    const float* bv      = (const float*)d_in[9];
    const float* Wo      = (const float*)d_in[10];
    const float* bo      = (const float*)d_in[11];
    const float* pos_emb = (const float*)d_in[12];

    __nv_bfloat16 *ah, *al, *wh, *wl, *qh, *ql, *kh, *kl, *vh, *vl, *eh, *el;
    cudaGetSymbolAddress((void**)&ah, g_ah);
    cudaGetSymbolAddress((void**)&al, g_al);
    cudaGetSymbolAddress((void**)&wh, g_wh);
    cudaGetSymbolAddress((void**)&wl, g_wl);
    cudaGetSymbolAddress((void**)&qh, g_qh);
    cudaGetSymbolAddress((void**)&ql, g_ql);
    cudaGetSymbolAddress((void**)&kh, g_kh);
    cudaGetSymbolAddress((void**)&kl, g_kl);
    cudaGetSymbolAddress((void**)&vh, g_vh);
    cudaGetSymbolAddress((void**)&vl, g_vl);
    cudaGetSymbolAddress((void**)&eh, g_eh);
    cudaGetSymbolAddress((void**)&el, g_el);

    cudaFuncSetAttribute(gemm_split<0>,
                         cudaFuncAttributeMaxDynamicSharedMemorySize, GSMEM_BYTES);
    cudaFuncSetAttribute(gemm_split<1>,
                         cudaFuncAttributeMaxDynamicSharedMemorySize, GSMEM_BYTES);
    cudaFuncSetAttribute(attn_split,
                         cudaFuncAttributeMaxDynamicSharedMemorySize, ASM_BYTES);

    const int NIN = MROWS * DM;   // 4M
    const int NW  = DM * DM;      // 1M
    dim3 ggrid(DM / 128, MROWS / 128);   // (8, 32)

    // Q projection (arena: input split -> A, weight split -> W, then GEMM)
    split_kernel<<<NIN / 1024, 256>>>(q_in, ah, al, NIN);
    split_kernel<<<NW / 1024, 256>>>(Wq, wh, wl, NW);
    gemm_split<0><<<ggrid, 256, GSMEM_BYTES>>>(ah, al, wh, wl, bq, nullptr, qh, ql);

    // K projection
    split_kernel<<<NIN / 1024, 256>>>(k_in, ah, al, NIN);
    split_kernel<<<NW / 1024, 256>>>(Wk, wh, wl, NW);
    gemm_split<0><<<ggrid, 256, GSMEM_BYTES>>>(ah, al, wh, wl, bk, nullptr, kh, kl);

    // V projection
    split_kernel<<<NIN / 1024, 256>>>(v_in, ah, al, NIN);
    split_kernel<<<NW / 1024, 256>>>(Wv, wh, wl, NW);
    gemm_split<0><<<ggrid, 256, GSMEM_BYTES>>>(ah, al, wh, wl, bv, nullptr, vh, vl);

    // pos_emb split
    split_kernel<<<(MAXSEQ * DH) / 1024, 256>>>(pos_emb, eh, el, MAXSEQ * DH);

    // Attention (writes output split into g_ah/g_al — input splits now dead)
    attn_split<<<dim3(16, N_B * NH), 256, ASM_BYTES>>>();

    // Output projection
    split_kernel<<<NW / 1024, 256>>>(Wo, wh, wl, NW);
    gemm_split<1><<<ggrid, 256, GSMEM_BYTES>>>(ah, al, wh, wl, bo,
                                               (float*)d_out, nullptr, nullptr);
}

// round 10
// speedup vs baseline: 2.3336x; 1.0236x over previous
#include <cuda_runtime.h>
#include <cuda_bf16.h>

// Problem constants
#define N_B   4
#define L_SEQ 1024
#define DM    1024
#define NH    16
#define DH    64
#define MROWS (N_B * L_SEQ)   // 4096
#define MAXSEQ 2048
#define HSZ   (N_B * NH * L_SEQ * DH)   // 4M

// ---------------------------------------------------------------------------
// Global scratch (split bf16 hi/lo pairs) — arena-reused, ~72 MB total
// ---------------------------------------------------------------------------
__device__ __nv_bfloat16 g_ah[MROWS * DM], g_al[MROWS * DM];  // input split / attn out
__device__ __nv_bfloat16 g_wh[DM * DM],    g_wl[DM * DM];     // current weight split
__device__ __nv_bfloat16 g_qh[HSZ], g_ql[HSZ];                // head-split Q
__device__ __nv_bfloat16 g_kh[HSZ], g_kl[HSZ];
__device__ __nv_bfloat16 g_vh[HSZ], g_vl[HSZ];
__device__ __nv_bfloat16 g_eh[MAXSEQ * DH], g_el[MAXSEQ * DH];// pos_emb

// ---------------------------------------------------------------------------
// helpers
// ---------------------------------------------------------------------------
__device__ __forceinline__ void bsplit(float x, __nv_bfloat16& h, __nv_bfloat16& l) {
    h = __float2bfloat16(x);
    l = __float2bfloat16(x - __bfloat162float(h));
}

// D(16x8,f32) += A(16x16,bf16,row) * B(16x8,bf16,col)
__device__ __forceinline__ void mma16(float* c, const unsigned* a, const unsigned* b) {
    asm volatile(
        "mma.sync.aligned.m16n8k16.row.col.f32.bf16.bf16.f32 "
        "{%0,%1,%2,%3}, {%4,%5,%6,%7}, {%8,%9}, {%0,%1,%2,%3};"
        : "+f"(c[0]), "+f"(c[1]), "+f"(c[2]), "+f"(c[3])
        : "r"(a[0]), "r"(a[1]), "r"(a[2]), "r"(a[3]), "r"(b[0]), "r"(b[1]));
}

__device__ __forceinline__ void cp16(void* dst, const void* src) {
    unsigned d = (unsigned)__cvta_generic_to_shared(dst);
    asm volatile("cp.async.cg.shared.global [%0], [%1], 16;" :: "r"(d), "l"(src));
}

// A fragment from row-major [m][k] tile; SW = stride in 32-bit words.
template <int SW>
__device__ __forceinline__ void ldA(const __nv_bfloat16* T, int r, int kw, int col, unsigned* a) {
    const unsigned* w = reinterpret_cast<const unsigned*>(T) + r * SW + kw + col;
    a[0] = w[0]; a[1] = w[8 * SW]; a[2] = w[4]; a[3] = w[8 * SW + 4];
}
// B fragment from row-major [n][k] tile (k contiguous); SW = word stride.
template <int SW>
__device__ __forceinline__ void ldB(const __nv_bfloat16* T, int n, int kw, int col, unsigned* b) {
    const unsigned* w = reinterpret_cast<const unsigned*>(T) + n * SW + kw + col;
    b[0] = w[0]; b[1] = w[4];
}
// B fragment from row-major [k][n] tile (transposed read); SH = stride in halves.
template <int SH>
__device__ __forceinline__ void ldBt(const __nv_bfloat16* T, int k, int n, unsigned* b) {
    const unsigned short* p = reinterpret_cast<const unsigned short*>(T) + k * SH + n;
    b[0] = (unsigned)p[0]      | ((unsigned)p[SH]     << 16);
    b[1] = (unsigned)p[8 * SH] | ((unsigned)p[9 * SH] << 16);
}

// ---------------------------------------------------------------------------
// Elementwise fp32 -> (bf16 hi, bf16 lo) split
// ---------------------------------------------------------------------------
__global__ void __launch_bounds__(256) split_kernel(
    const float* __restrict__ in, __nv_bfloat16* __restrict__ h,
    __nv_bfloat16* __restrict__ l, int n)
{
    int i = (blockIdx.x * 256 + threadIdx.x) * 4;
    if (i >= n) return;
    float4 v = *reinterpret_cast<const float4*>(in + i);
    __nv_bfloat16 h0, h1, h2, h3, l0, l1, l2, l3;
    bsplit(v.x, h0, l0); bsplit(v.y, h1, l1);
    bsplit(v.z, h2, l2); bsplit(v.w, h3, l3);
    *reinterpret_cast<__nv_bfloat162*>(h + i)     = __nv_bfloat162(h0, h1);
    *reinterpret_cast<__nv_bfloat162*>(h + i + 2) = __nv_bfloat162(h2, h3);
    *reinterpret_cast<__nv_bfloat162*>(l + i)     = __nv_bfloat162(l0, l1);
    *reinterpret_cast<__nv_bfloat162*>(l + i + 2) = __nv_bfloat162(l2, l3);
}

// ---------------------------------------------------------------------------
// Split-bf16 GEMM: C[4096,1024] = (Ah+Al) @ (Wh+Wl) + bias
// (unchanged — known good)
// ---------------------------------------------------------------------------
#define GBK  32
#define GAS  40     // A tile stride (bf16)
#define GBS  136    // B tile stride (bf16)
#define GA_SZ (128 * GAS)   // 5120 bf16 per component
#define GB_SZ (GBK * GBS)   // 4352 bf16 per component
#define GBUF  (2 * GA_SZ + 2 * GB_SZ)
#define GSMEM_BYTES (2 * GBUF * 2)   // 75776

template <int MODE>
__global__ void __launch_bounds__(256) gemm_split(
    const __nv_bfloat16* __restrict__ Agh, const __nv_bfloat16* __restrict__ Agl,
    const __nv_bfloat16* __restrict__ Wgh, const __nv_bfloat16* __restrict__ Wgl,
    const float* __restrict__ bias, float* __restrict__ C32,
    __nv_bfloat16* __restrict__ Cbh, __nv_bfloat16* __restrict__ Cbl)
{
    extern __shared__ __nv_bfloat16 gsm[];

    const int tid  = threadIdx.x;
    const int lane = tid & 31, wid = tid >> 5;
    const int row  = lane >> 2, col = lane & 3;
    const int wm   = (wid & 1) << 6;
    const int wn   = (wid >> 1) << 5;
    const int row0 = blockIdx.y << 7;
    const int col0 = blockIdx.x << 7;

    float acc[4][4][4];
#pragma unroll
    for (int i = 0; i < 4; i++)
#pragma unroll
        for (int j = 0; j < 4; j++)
#pragma unroll
            for (int k = 0; k < 4; k++) acc[i][j][k] = 0.f;

    auto fill = [&](int buf, int k0) {
        __nv_bfloat16* Ah = gsm + buf * GBUF;
        __nv_bfloat16* Al = Ah + GA_SZ;
        __nv_bfloat16* Bh = Al + GA_SZ;
        __nv_bfloat16* Bl = Bh + GB_SZ;
#pragma unroll
        for (int i = 0; i < 2; i++) {
            int f = tid + i * 256;          // 0..511
            int m = f >> 2, ch = f & 3;
            cp16(Ah + m * GAS + ch * 8, Agh + (size_t)(row0 + m) * DM + k0 + ch * 8);
            cp16(Al + m * GAS + ch * 8, Agl + (size_t)(row0 + m) * DM + k0 + ch * 8);
        }
#pragma unroll
        for (int i = 0; i < 2; i++) {
            int f = tid + i * 256;          // 0..511
            int kk = f >> 4, ch = f & 15;
            cp16(Bh + kk * GBS + ch * 8, Wgh + (size_t)(k0 + kk) * DM + col0 + ch * 8);
            cp16(Bl + kk * GBS + ch * 8, Wgl + (size_t)(k0 + kk) * DM + col0 + ch * 8);
        }
        asm volatile("cp.async.commit_group;");
    };

    fill(0, 0);

    for (int t = 0; t < DM / GBK; t++) {
        const int buf = t & 1;
        if (t + 1 < DM / GBK) {
            fill(buf ^ 1, (t + 1) * GBK);
            asm volatile("cp.async.wait_group 1;");
        } else {
            asm volatile("cp.async.wait_group 0;");
        }
        __syncthreads();

        const __nv_bfloat16* Ah = gsm + buf * GBUF;
        const __nv_bfloat16* Al = Ah + GA_SZ;
        const __nv_bfloat16* Bh = Al + GA_SZ;
        const __nv_bfloat16* Bl = Bh + GB_SZ;

#pragma unroll
        for (int ks = 0; ks < GBK / 16; ks++) {
            unsigned ah[4][4], al[4][4], bh[4][2], bl[4][2];
#pragma unroll
            for (int i = 0; i < 4; i++) {
                ldA<GAS / 2>(Ah, wm + i * 16 + row, ks * 8, col, ah[i]);
                ldA<GAS / 2>(Al, wm + i * 16 + row, ks * 8, col, al[i]);
            }
            const int kb = ks * 16 + col * 2;
#pragma unroll
            for (int j = 0; j < 4; j++) {
                ldBt<GBS>(Bh, kb, wn + j * 8 + row, bh[j]);
                ldBt<GBS>(Bl, kb, wn + j * 8 + row, bl[j]);
            }
#pragma unroll
            for (int i = 0; i < 4; i++)
#pragma unroll
                for (int j = 0; j < 4; j++) {
                    mma16(acc[i][j], ah[i], bh[j]);
                    mma16(acc[i][j], ah[i], bl[j]);
                    mma16(acc[i][j], al[i], bh[j]);
                }
        }
        __syncthreads();
    }

    // Epilogue
#pragma unroll
    for (int i = 0; i < 4; i++) {
#pragma unroll
        for (int j = 0; j < 4; j++) {
            int r = row0 + wm + i * 16 + row;
            int c = col0 + wn + j * 8 + 2 * col;
            float bx = bias[c], by = bias[c + 1];
            float v00 = acc[i][j][0] + bx, v01 = acc[i][j][1] + by;
            float v10 = acc[i][j][2] + bx, v11 = acc[i][j][3] + by;
            if (MODE == 0) {
                int n = r >> 10, h = c >> 6, d = c & 63;
                int l0 = r & 1023, l1 = (r + 8) & 1023;
                size_t i0 = ((size_t)((n * NH + h) * L_SEQ + l0) << 6) + d;
                size_t i1 = ((size_t)((n * NH + h) * L_SEQ + l1) << 6) + d;
                __nv_bfloat16 h0, h1, lo0, lo1;
                bsplit(v00, h0, lo0); bsplit(v01, h1, lo1);
                *reinterpret_cast<__nv_bfloat162*>(Cbh + i0) = __nv_bfloat162(h0, h1);
                *reinterpret_cast<__nv_bfloat162*>(Cbl + i0) = __nv_bfloat162(lo0, lo1);
                bsplit(v10, h0, lo0); bsplit(v11, h1, lo1);
                *reinterpret_cast<__nv_bfloat162*>(Cbh + i1) = __nv_bfloat162(h0, h1);
                *reinterpret_cast<__nv_bfloat162*>(Cbl + i1) = __nv_bfloat162(lo0, lo1);
            } else {
                *reinterpret_cast<float2*>(&C32[(size_t)r * DM + c]) = make_float2(v00, v01);
                *reinterpret_cast<float2*>(&C32[(size_t)(r + 8) * DM + c]) = make_float2(v10, v11);
            }
        }
    }
}

// ---------------------------------------------------------------------------
// Split-bf16 flash attention, v2:
//  - E tiles as 2 persistent 64-row chunks, sliding window (half the E traffic),
//    next chunk prefetched right after phase B (latency hidden).
//  - QE stored as diagonal band (64x68 fp32).
//  - P overwrites the dead K buffer; V has its own buffer loaded in phase A.
// Block = (n,h, 64-row q-tile), 256 threads (8 warps).
// ---------------------------------------------------------------------------
#define AST 72              // bf16 stride for tiles
#define ASW (AST / 2)       // 36 words
#define TQ  (64 * AST)      // 4608 bf16 per component
// bytes: bf16 10*TQ*2 = 92160; QEb 64*68*4 = 17408; red 384*4 = 1536
#define ASM_BYTES (10 * TQ * 2 + 64 * 68 * 4 + 384 * 4)   // 111104

__global__ void __launch_bounds__(256) attn_split()
{
    extern __shared__ __nv_bfloat16 asm_[];
    __nv_bfloat16* Qh = asm_;              // [64][72]
    __nv_bfloat16* Ql = Qh + TQ;
    __nv_bfloat16* Kh = Ql + TQ;           // [64][72]  K[b][d] -> P[a][b]
    __nv_bfloat16* Kl = Kh + TQ;
    __nv_bfloat16* Vh = Kl + TQ;           // [64][72]  V[b][c]
    __nv_bfloat16* Vl = Vh + TQ;
    __nv_bfloat16* Eh = Vl + TQ;           // [2][64][72] chunked E
    __nv_bfloat16* El = Eh + 2 * TQ;
    float* QEb   = reinterpret_cast<float*>(El + 2 * TQ);  // [64][68] band
    float* pmax  = QEb + 64 * 68;          // [2][64]
    float* psum  = pmax + 128;             // [2][64]
    float* m_run = psum + 128;             // [64]
    float* l_run = m_run + 64;             // [64]

    const int tid  = threadIdx.x;
    const int lane = tid & 31, wid = tid >> 5;
    const int row  = lane >> 2, col = lane & 3;

    const int qt  = 15 - blockIdx.x;   // heavy tiles first
    const int nh  = blockIdx.y;
    const int qt0 = qt * 64;
    const size_t headbase = (size_t)nh * L_SEQ * DH;

    const int wmB = (wid & 1) * 32;
    const int wnB = (wid >> 1) * 32;       // 0,32,64,96
    const int chunkbitB = wnB >> 6;        // 0 for cols<64, 1 for cols>=64
    const int wnBl = wnB & 63;             // local col within chunk
    const int wmC = (wid & 3) * 16;
    const int wnC4 = wid >> 2;
    const int wnC = wnC4 * 32;
    const int r1 = wmC + row, r2 = r1 + 8;

    if (tid < 64) { m_run[tid] = -1e30f; l_run[tid] = 0.f; }

    // Q tile (cp.async)
    {
        const size_t base = headbase + (size_t)qt0 * DH;
#pragma unroll
        for (int i = 0; i < 2; i++) {
            int f = tid + i * 256;      // 0..511
            int a = f >> 3, ch = f & 7;
            cp16(Qh + a * AST + ch * 8, g_qh + base + a * DH + ch * 8);
            cp16(Ql + a * AST + ch * 8, g_ql + base + a * DH + ch * 8);
        }
        asm volatile("cp.async.commit_group;");
    }

    float o[4][4];
#pragma unroll
    for (int j = 0; j < 4; j++)
#pragma unroll
        for (int k = 0; k < 4; k++) o[j][k] = 0.f;

    const int r0base = 1984 - qt0;   // E row origin at kt=0

    for (int kt = 0; kt <= qt; kt++) {
        const int kt0 = kt * 64;
        const int r0  = r0base + kt0;
        const int dqk = qt0 - kt0;
        const int par = kt & 1;          // logical chunk0 -> physical chunk par

        // ---- phase A: cp.async K, V (and both E chunks on first tile) ----
        {
            const size_t baseK = headbase + (size_t)kt0 * DH;
#pragma unroll
            for (int i = 0; i < 2; i++) {
                int f = tid + i * 256;
                int b = f >> 3, ch = f & 7;
                cp16(Kh + b * AST + ch * 8, g_kh + baseK + b * DH + ch * 8);
                cp16(Kl + b * AST + ch * 8, g_kl + baseK + b * DH + ch * 8);
            }
#pragma unroll
            for (int i = 0; i < 2; i++) {
                int f = tid + i * 256;
                int b = f >> 3, ch = f & 7;
                cp16(Vh + b * AST + ch * 8, g_vh + baseK + b * DH + ch * 8);
                cp16(Vl + b * AST + ch * 8, g_vl + baseK + b * DH + ch * 8);
            }
            if (kt == 0) {
#pragma unroll
                for (int i = 0; i < 4; i++) {
                    int f = tid + i * 256;      // 0..1023
                    int c = f >> 3, ch = f & 7; // c 0..127
                    int r = r0 + c;
                    r = (r < MAXSEQ) ? r : (MAXSEQ - 1);
                    int phys = c >> 6;          // par==0 at kt=0
                    int cl   = c & 63;
                    cp16(Eh + phys * TQ + cl * AST + ch * 8, g_eh + (size_t)r * DH + ch * 8);
                    cp16(El + phys * TQ + cl * AST + ch * 8, g_el + (size_t)r * DH + ch * 8);
                }
            }
            asm volatile("cp.async.commit_group;");
            asm volatile("cp.async.wait_group 0;");
        }
        __syncthreads();                                    // [sync1]

        // ---- phase B: QE = Q @ E^T (chunked), store diagonal band ----
        {
            const __nv_bfloat16* Ebh = Eh + (chunkbitB ^ par) * TQ;
            const __nv_bfloat16* Ebl = El + (chunkbitB ^ par) * TQ;
            float qe[2][4][4];
#pragma unroll
            for (int i = 0; i < 2; i++)
#pragma unroll
                for (int j = 0; j < 4; j++)
#pragma unroll
                    for (int k = 0; k < 4; k++) qe[i][j][k] = 0.f;
#pragma unroll
            for (int ks = 0; ks < 4; ks++) {
                unsigned ah[2][4], al[2][4], bh[4][2], bl[4][2];
#pragma unroll
                for (int i = 0; i < 2; i++) {
                    ldA<ASW>(Qh, wmB + i * 16 + row, ks * 8, col, ah[i]);
                    ldA<ASW>(Ql, wmB + i * 16 + row, ks * 8, col, al[i]);
                }
#pragma unroll
                for (int j = 0; j < 4; j++) {
                    ldB<ASW>(Ebh, wnBl + j * 8 + row, ks * 8, col, bh[j]);
                    ldB<ASW>(Ebl, wnBl + j * 8 + row, ks * 8, col, bl[j]);
                }
#pragma unroll
                for (int i = 0; i < 2; i++)
#pragma unroll
                    for (int j = 0; j < 4; j++) {
                        mma16(qe[i][j], ah[i], bh[j]);
                        mma16(qe[i][j], ah[i], bl[j]);
                        mma16(qe[i][j], al[i], bh[j]);
                    }
            }
            // store band: QEb[a][b], b = cc - 63 + a (valid 0..63)
#pragma unroll
            for (int i = 0; i < 2; i++) {
                int aa = wmB + i * 16 + row;
#pragma unroll
                for (int j = 0; j < 4; j++) {
                    int cc = wnB + j * 8 + 2 * col;
                    int b00 = cc - 63 + aa;
                    int b10 = b00 + 8;          // row aa+8
                    if ((unsigned)b00 < 64u)       QEb[aa * 68 + b00]           = qe[i][j][0];
                    if ((unsigned)(b00 + 1) < 64u) QEb[aa * 68 + b00 + 1]       = qe[i][j][1];
                    if ((unsigned)b10 < 64u)       QEb[(aa + 8) * 68 + b10]     = qe[i][j][2];
                    if ((unsigned)(b10 + 1) < 64u) QEb[(aa + 8) * 68 + b10 + 1] = qe[i][j][3];
                }
            }
        }
        __syncthreads();                                    // [sync2]

        // ---- prefetch next E chunk (overwrites chunk `par`, dead after B) ----
        if (kt < qt) {
#pragma unroll
            for (int i = 0; i < 2; i++) {
                int f = tid + i * 256;          // 0..511
                int c2 = f >> 3, ch = f & 7;    // c2 0..63
                int r = r0 + 128 + c2;
                r = (r < MAXSEQ) ? r : (MAXSEQ - 1);
                cp16(Eh + par * TQ + c2 * AST + ch * 8, g_eh + (size_t)r * DH + ch * 8);
                cp16(El + par * TQ + c2 * AST + ch * 8, g_el + (size_t)r * DH + ch * 8);
            }
            asm volatile("cp.async.commit_group;");
        }

        // ---- phase C: S = Q @ K^T, bias, mask, online softmax ----
        float s[4][4];
#pragma unroll
        for (int j = 0; j < 4; j++)
#pragma unroll
            for (int k = 0; k < 4; k++) s[j][k] = 0.f;
#pragma unroll
        for (int ks = 0; ks < 4; ks++) {
            unsigned ah[4], al[4], bh[4][2], bl[4][2];
            ldA<ASW>(Qh, wmC + row, ks * 8, col, ah);
            ldA<ASW>(Ql, wmC + row, ks * 8, col, al);
#pragma unroll
            for (int j = 0; j < 4; j++) {
                ldB<ASW>(Kh, wnC + j * 8 + row, ks * 8, col, bh[j]);
                ldB<ASW>(Kl, wnC + j * 8 + row, ks * 8, col, bl[j]);
            }
#pragma unroll
            for (int j = 0; j < 4; j++) {
                mma16(s[j], ah, bh[j]);
                mma16(s[j], ah, bl[j]);
                mma16(s[j], al, bh[j]);
            }
        }
        {
            const int limit1 = dqk + r1, limit2 = dqk + r2;
            float mx1 = -1e30f, mx2 = -1e30f;
#pragma unroll
            for (int j = 0; j < 4; j++) {
                int bb = wnC + j * 8 + 2 * col;
                float qe10 = QEb[r1 * 68 + bb];
                float qe11 = QEb[r1 * 68 + bb + 1];
                float qe20 = QEb[r2 * 68 + bb];
                float qe21 = QEb[r2 * 68 + bb + 1];
                s[j][0] = (bb     <= limit1) ? (s[j][0] + qe10) * 0.125f : -1e30f;
                s[j][1] = (bb + 1 <= limit1) ? (s[j][1] + qe11) * 0.125f : -1e30f;
                s[j][2] = (bb     <= limit2) ? (s[j][2] + qe20) * 0.125f : -1e30f;
                s[j][3] = (bb + 1 <= limit2) ? (s[j][3] + qe21) * 0.125f : -1e30f;
                mx1 = fmaxf(mx1, fmaxf(s[j][0], s[j][1]));
                mx2 = fmaxf(mx2, fmaxf(s[j][2], s[j][3]));
            }
            mx1 = fmaxf(mx1, __shfl_xor_sync(0xffffffffu, mx1, 1));
            mx1 = fmaxf(mx1, __shfl_xor_sync(0xffffffffu, mx1, 2));
            mx2 = fmaxf(mx2, __shfl_xor_sync(0xffffffffu, mx2, 1));
            mx2 = fmaxf(mx2, __shfl_xor_sync(0xffffffffu, mx2, 2));
            if (col == 0) {
                pmax[wnC4 * 64 + r1] = mx1;
                pmax[wnC4 * 64 + r2] = mx2;
            }
            __syncthreads();                                // [sync3] also: all K reads done

            float newm1 = fmaxf(m_run[r1], fmaxf(pmax[r1], pmax[64 + r1]));
            float newm2 = fmaxf(m_run[r2], fmaxf(pmax[r2], pmax[64 + r2]));
            float alpha1 = __expf(m_run[r1] - newm1);
            float alpha2 = __expf(m_run[r2] - newm2);
            float sum1 = 0.f, sum2 = 0.f;
#pragma unroll
            for (int j = 0; j < 4; j++) {
                int bb = wnC + j * 8 + 2 * col;
                float p0 = __expf(s[j][0] - newm1);
                float p1 = __expf(s[j][1] - newm1);
                float p2 = __expf(s[j][2] - newm2);
                float p3 = __expf(s[j][3] - newm2);
                sum1 += p0 + p1; sum2 += p2 + p3;
                __nv_bfloat16 h0, h1, l0, l1;
                bsplit(p0, h0, l0); bsplit(p1, h1, l1);
                *reinterpret_cast<__nv_bfloat162*>(&Kh[r1 * AST + bb]) = __nv_bfloat162(h0, h1);
                *reinterpret_cast<__nv_bfloat162*>(&Kl[r1 * AST + bb]) = __nv_bfloat162(l0, l1);
                bsplit(p2, h0, l0); bsplit(p3, h1, l1);
                *reinterpret_cast<__nv_bfloat162*>(&Kh[r2 * AST + bb]) = __nv_bfloat162(h0, h1);
                *reinterpret_cast<__nv_bfloat162*>(&Kl[r2 * AST + bb]) = __nv_bfloat162(l0, l1);
            }
            sum1 += __shfl_xor_sync(0xffffffffu, sum1, 1);
            sum1 += __shfl_xor_sync(0xffffffffu, sum1, 2);
            sum2 += __shfl_xor_sync(0xffffffffu, sum2, 1);
            sum2 += __shfl_xor_sync(0xffffffffu, sum2, 2);
            if (col == 0) {
                psum[wnC4 * 64 + r1] = sum1;
                psum[wnC4 * 64 + r2] = sum2;
            }
#pragma unroll
            for (int j = 0; j < 4; j++) {
                o[j][0] *= alpha1; o[j][1] *= alpha1;
                o[j][2] *= alpha2; o[j][3] *= alpha2;
            }
            __syncthreads();                                // [sync4] psum/P ready

            if (wnC4 == 0 && col == 0) {
                l_run[r1] = l_run[r1] * alpha1 + psum[r1] + psum[64 + r1];
                l_run[r2] = l_run[r2] * alpha2 + psum[r2] + psum[64 + r2];
                m_run[r1] = newm1;
                m_run[r2] = newm2;
            }
        }

        // ---- phase E: O += P @ V  (P in K buffer; B-frag = V^T via u16) ----
#pragma unroll
        for (int ks = 0; ks < 4; ks++) {
            unsigned ah[4], al[4], bh[4][2], bl[4][2];
            ldA<ASW>(Kh, wmC + row, ks * 8, col, ah);   // P hi
            ldA<ASW>(Kl, wmC + row, ks * 8, col, al);   // P lo
            const int kb = ks * 16 + col * 2;
#pragma unroll
            for (int j = 0; j < 4; j++) {
                ldBt<AST>(Vh, kb, wnC + j * 8 + row, bh[j]);
                ldBt<AST>(Vl, kb, wnC + j * 8 + row, bl[j]);
            }
#pragma unroll
            for (int j = 0; j < 4; j++) {
                mma16(o[j], ah, bh[j]);
                mma16(o[j], ah, bl[j]);
                mma16(o[j], al, bh[j]);
            }
        }
        __syncthreads();                                    // [sync5] K/V free
    }

    // Epilogue: normalize, split, write g_ah/g_al [n][l][h*64+c]
    {
        const int n = nh >> 4, h = nh & 15;
        float inv1 = 1.f / l_run[r1];
        float inv2 = 1.f / l_run[r2];
#pragma unroll
        for (int j = 0; j < 4; j++) {
            int cc = wnC + j * 8 + 2 * col;
            size_t a1 = (size_t)(n * L_SEQ + qt0 + r1) * DM + h * DH + cc;
            size_t a2 = (size_t)(n * L_SEQ + qt0 + r2) * DM + h * DH + cc;
            __nv_bfloat16 h0, h1, l0, l1;
            bsplit(o[j][0] * inv1, h0, l0); bsplit(o[j][1] * inv1, h1, l1);
            *reinterpret_cast<__nv_bfloat162*>(g_ah + a1) = __nv_bfloat162(h0, h1);
            *reinterpret_cast<__nv_bfloat162*>(g_al + a1) = __nv_bfloat162(l0, l1);
            bsplit(o[j][2] * inv2, h0, l0); bsplit(o[j][3] * inv2, h1, l1);
            *reinterpret_cast<__nv_bfloat162*>(g_ah + a2) = __nv_bfloat162(h0, h1);
            *reinterpret_cast<__nv_bfloat162*>(g_al + a2) = __nv_bfloat162(l0, l1);
        }
    }
}

// ---------------------------------------------------------------------------
extern "C" void kernel_launch(void* const* d_in, const int* in_sizes, int n_in,
                              void* d_out, int out_size)
{
    const float* q_in    = (const float*)d_in[0];
    const float* k_in    = (const float*)d_in[1];
    const float* v_in    = (const float*)d_in[2];
    // d_in[3] = mask (strict causal; analytic)
    const float* Wq      = (const float*)d_in[4];
    const float* bq      = (const float*)d_in[5];
    const float* Wk      = (const float*)d_in[6];
    const float* bk      = (const float*)d_in[7];
    const float* Wv      = (const float*)d_in[8];
    const float* bv      = (const float*)d_in[9];
    const float* Wo      = (const float*)d_in[10];
    const float* bo      = (const float*)d_in[11];
    const float* pos_emb = (const float*)d_in[12];

    __nv_bfloat16 *ah, *al, *wh, *wl, *qh, *ql, *kh, *kl, *vh, *vl, *eh, *el;
    cudaGetSymbolAddress((void**)&ah, g_ah);
    cudaGetSymbolAddress((void**)&al, g_al);
    cudaGetSymbolAddress((void**)&wh, g_wh);
    cudaGetSymbolAddress((void**)&wl, g_wl);
    cudaGetSymbolAddress((void**)&qh, g_qh);
    cudaGetSymbolAddress((void**)&ql, g_ql);
    cudaGetSymbolAddress((void**)&kh, g_kh);
    cudaGetSymbolAddress((void**)&kl, g_kl);
    cudaGetSymbolAddress((void**)&vh, g_vh);
    cudaGetSymbolAddress((void**)&vl, g_vl);
    cudaGetSymbolAddress((void**)&eh, g_eh);
    cudaGetSymbolAddress((void**)&el, g_el);

    cudaFuncSetAttribute(gemm_split<0>,
                         cudaFuncAttributeMaxDynamicSharedMemorySize, GSMEM_BYTES);
    cudaFuncSetAttribute(gemm_split<1>,
                         cudaFuncAttributeMaxDynamicSharedMemorySize, GSMEM_BYTES);
    cudaFuncSetAttribute(attn_split,
                         cudaFuncAttributeMaxDynamicSharedMemorySize, ASM_BYTES);

    const int NIN = MROWS * DM;   // 4M
    const int NW  = DM * DM;      // 1M
    dim3 ggrid(DM / 128, MROWS / 128);   // (8, 32)

    // Q projection (arena: input split -> A, weight split -> W, then GEMM)
    split_kernel<<<NIN / 1024, 256>>>(q_in, ah, al, NIN);
    split_kernel<<<NW / 1024, 256>>>(Wq, wh, wl, NW);
    gemm_split<0><<<ggrid, 256, GSMEM_BYTES>>>(ah, al, wh, wl, bq, nullptr, qh, ql);

    // K projection
    split_kernel<<<NIN / 1024, 256>>>(k_in, ah, al, NIN);
    split_kernel<<<NW / 1024, 256>>>(Wk, wh, wl, NW);
    gemm_split<0><<<ggrid, 256, GSMEM_BYTES>>>(ah, al, wh, wl, bk, nullptr, kh, kl);

    // V projection
    split_kernel<<<NIN / 1024, 256>>>(v_in, ah, al, NIN);
    split_kernel<<<NW / 1024, 256>>>(Wv, wh, wl, NW);
    gemm_split<0><<<ggrid, 256, GSMEM_BYTES>>>(ah, al, wh, wl, bv, nullptr, vh, vl);

    // pos_emb split
    split_kernel<<<(MAXSEQ * DH) / 1024, 256>>>(pos_emb, eh, el, MAXSEQ * DH);

    // Attention (writes output split into g_ah/g_al — input splits now dead)
    attn_split<<<dim3(16, N_B * NH), 256, ASM_BYTES>>>();

    // Output projection
    split_kernel<<<NW / 1024, 256>>>(Wo, wh, wl, NW);
    gemm_split<1><<<ggrid, 256, GSMEM_BYTES>>>(ah, al, wh, wl, bo,
                                               (float*)d_out, nullptr, nullptr);
}